// round 15
// baseline (speedup 1.0000x reference)
#include <cuda_runtime.h>
#include <cuda_bf16.h>
#include <cuda_fp16.h>
#include <math.h>
#include <stdint.h>

// ---------------------------------------------------------------------------
// Aggregator: relational graph attention, tensor-core (warp mma.sync) version.
//   Y[r]     = ego @ W[r]            (bf16 HMMA, fp32 accumulate, fp16 store)
//   s_e      = leaky_relu( Y[et_e, h_e] . ego[t_e] )
//   out[n]   = sum_e exp(s_e) * ego[t_e]  /  ( den[n] * max(cnt[n],1) )
// GEMM: one CTA per (128-row tile, relation-quad) -> 4-iteration serial loop,
// 4x the CTA parallelism of the all-16 version. Y stores staged through smem
// for coalesced 128B lines.
// ---------------------------------------------------------------------------

#define N_CAP   131072
#define YROWS   102400               // >= N, multiple of 128
__device__ __half g_Yh[16u * YROWS * 64u];     // [R, N, 64] fp16
__device__ __half g_egoh[(size_t)N_CAP * 64];  // [N, 64] fp16 mirror of ego
__device__ float2 g_dencnt[N_CAP];             // (den, cnt) per head node

// pre-transposed W (row n, col k), padded row stride AS, bf16
#define AS 72
__device__ __nv_bfloat16 g_Wt[16 * 64 * AS];

__device__ __forceinline__ uint32_t smem_u32(const void* p) {
    uint32_t a;
    asm("{ .reg .u64 t; cvta.to.shared.u64 t, %1; cvt.u32.u64 %0, t; }"
        : "=r"(a) : "l"(p));
    return a;
}
__device__ __forceinline__ void ldm_x4(uint32_t* r, uint32_t addr) {
    asm volatile("ldmatrix.sync.aligned.m8n8.x4.shared.b16 {%0,%1,%2,%3}, [%4];"
                 : "=r"(r[0]), "=r"(r[1]), "=r"(r[2]), "=r"(r[3]) : "r"(addr));
}
__device__ __forceinline__ void mma_bf16(float* c, const uint32_t* a,
                                         uint32_t b0, uint32_t b1) {
    asm volatile(
        "mma.sync.aligned.m16n8k16.row.col.f32.bf16.bf16.f32 "
        "{%0,%1,%2,%3}, {%4,%5,%6,%7}, {%8,%9}, {%0,%1,%2,%3};"
        : "+f"(c[0]), "+f"(c[1]), "+f"(c[2]), "+f"(c[3])
        : "r"(a[0]), "r"(a[1]), "r"(a[2]), "r"(a[3]), "r"(b0), "r"(b1));
}
__device__ __forceinline__ uint32_t pack2(float x0, float x1) {
    return ((uint32_t)__bfloat16_as_ushort(__float2bfloat16(x1)) << 16)
         | (uint32_t)__bfloat16_as_ushort(__float2bfloat16(x0));
}

// smem layout (bytes): region0 = A tile, later reused as Y staging
//   (128 rows x AS halves = 18432B); region1 = B tile (9216B)
#define A_OFF   0
#define B_OFF   18432
#define SMEM_SZ (18432 + 9216 + 128)

// ============================ kernels ======================================

// ---- zero out + dencnt + fp16 ego mirror; blocks 0..15 also prep W --------
__global__ void zero_kernel(float4* __restrict__ out4,
                            const float4* __restrict__ ego4,
                            const float* __restrict__ Wg,
                            int n_out4, int n_dc4)
{
    int i = blockIdx.x * blockDim.x + threadIdx.x;
    if (i < n_out4) {
        out4[i] = make_float4(0.f, 0.f, 0.f, 0.f);
        float4 v = ego4[i];
        __half2 h0 = __floats2half2_rn(v.x, v.y);
        __half2 h1 = __floats2half2_rn(v.z, v.w);
        *(uint2*)(g_egoh + (size_t)i * 4) =
            make_uint2(*(uint32_t*)&h0, *(uint32_t*)&h1);
    }
    if (i < n_dc4) ((float4*)g_dencnt)[i] = make_float4(0.f, 0.f, 0.f, 0.f);

    if (blockIdx.x < 16) {           // W transpose to bf16, padded stride
        const int r = blockIdx.x;
        for (int idx = threadIdx.x; idx < 4096; idx += 256) {
            int k = idx >> 6, n = idx & 63;          // W[k][n], coalesced read
            float v = Wg[(size_t)r * 4096 + idx];
            g_Wt[r * 64 * AS + n * AS + k] = __float2bfloat16(v);
        }
    }
}

// ---- GEMM: one CTA per (tile, relation-quad); 4-iteration loop ------------
__global__ __launch_bounds__(256) void gemm_transform(
    const float* __restrict__ ego, int N)
{
    extern __shared__ __align__(16) char sm[];
    __nv_bfloat16* sh = (__nv_bfloat16*)sm;
    __half* stag = (__half*)sm;                  // staging aliases A region
    const uint32_t smb = smem_u32(sm);

    const int tid   = threadIdx.x;
    const int wid   = tid >> 5;
    const int lane  = tid & 31;
    const int rbase = (blockIdx.x & 3) * 4;      // relation quad
    const int tile  = blockIdx.x >> 2;           // adjacent CTAs share tile
    const int rows  = min(128, N - tile * 128);

    // --- stage A tile (ego rows) as bf16, zero-padded ----------------------
    for (int i = tid * 2; i < 128 * 64; i += 512) {
        int row = i >> 6, col = i & 63;
        float v0 = 0.f, v1 = 0.f;
        if (row < rows) {
            const float2 v = *(const float2*)(ego + ((size_t)(tile * 128 + row)) * 64 + col);
            v0 = v.x; v1 = v.y;
        }
        *(uint32_t*)(sh + row * AS + col) = pack2(v0, v1);
    }
    __syncthreads();

    // --- per-warp A fragment: 16 rows x K=64, held in registers ------------
    const int m0   = wid * 16;
    const int frow = (lane & 7) + ((lane >> 3) & 1) * 8;
    const int fcol = (lane >> 4) * 8;
    uint32_t Af[4][4];
    #pragma unroll
    for (int kt = 0; kt < 4; kt++) {
        uint32_t off = (uint32_t)((m0 + frow) * AS + kt * 16 + fcol) * 2;
        ldm_x4(Af[kt], smb + A_OFF + off);
    }

    const int g  = lane >> 2;         // output row within 8-group
    const int tq = lane & 3;          // output col pair

    #pragma unroll
    for (int rr = 0; rr < 4; rr++) {
        const int r = rbase + rr;
        // stage B = pre-transposed W_r (pure vector copies)
        {
            const uint4* src = (const uint4*)(g_Wt + r * 64 * AS);
            uint4* dst = (uint4*)(sm + B_OFF);
            #pragma unroll
            for (int k = 0; k < 3; k++) {
                int i = tid + k * 256;
                if (i < 576) dst[i] = src[i];
            }
        }
        __syncthreads();   // B staged; staging region free for reuse

        float acc[8][4];
        #pragma unroll
        for (int i = 0; i < 8; i++)
            #pragma unroll
            for (int j = 0; j < 4; j++) acc[i][j] = 0.f;

        #pragma unroll
        for (int nt = 0; nt < 4; nt++) {
            #pragma unroll
            for (int kt = 0; kt < 4; kt++) {
                uint32_t boff = (uint32_t)((nt * 16 + frow) * AS + kt * 16 + fcol) * 2;
                uint32_t Bf[4];
                ldm_x4(Bf, smb + B_OFF + boff);
                mma_bf16(acc[2 * nt],     Af[kt], Bf[0], Bf[2]);
                mma_bf16(acc[2 * nt + 1], Af[kt], Bf[1], Bf[3]);
            }
        }

        // --- STS fragments to staging (padded stride AS -> no row aliasing)
        {
            int row0 = m0 + g;
            #pragma unroll
            for (int nt8 = 0; nt8 < 8; nt8++) {
                int col = nt8 * 8 + tq * 2;
                __half2 ha = __floats2half2_rn(acc[nt8][0], acc[nt8][1]);
                __half2 hb = __floats2half2_rn(acc[nt8][2], acc[nt8][3]);
                *(__half2*)(stag + row0 * AS + col)       = ha;
                *(__half2*)(stag + (row0 + 8) * AS + col) = hb;
            }
        }
        __syncthreads();

        // --- coalesced Y writeback: full 128B lines ------------------------
        {
            uint32_t ybase = ((uint32_t)r * (uint32_t)N + (uint32_t)(tile * 128)) * 64u;
            #pragma unroll
            for (int q = 0; q < 4; q++) {
                int i = tid + q * 256;            // 1024 uint4 total
                int row = i >> 3, seg = i & 7;
                if (row < rows) {
                    uint4 v = *(const uint4*)(stag + row * AS + seg * 8);
                    *(uint4*)(g_Yh + ybase + (uint32_t)row * 64u + seg * 8) = v;
                }
            }
        }
        // next iteration's post-B-stage barrier orders staging reuse
    }
}

// ---- fused edge pass: 8 edges/warp (4 per half), fp16 gathers -------------
__global__ __launch_bounds__(256) void edge_pass(
    const int*   __restrict__ heads,
    const int*   __restrict__ tails,
    const int*   __restrict__ etype,
    float*       __restrict__ out,
    int N, int E)
{
    const int warp = (blockIdx.x * 256 + threadIdx.x) >> 5;
    const int lane = threadIdx.x & 31;
    const int half = lane >> 4;
    const int l2   = lane & 15;
    const unsigned hmask = 0xFFFFu << (half * 16);

    const int ebase = warp * 8 + half * 4;     // this half-warp: 4 edges
    if (ebase >= E) return;

    int4 hh, tt, rr;
    if (ebase + 3 < E) {
        hh = *(const int4*)(heads + ebase);
        tt = *(const int4*)(tails + ebase);
        rr = *(const int4*)(etype + ebase);
    } else {
        int* hp = (int*)&hh; int* tp = (int*)&tt; int* rp = (int*)&rr;
        #pragma unroll
        for (int j = 0; j < 4; j++) {
            int e = min(ebase + j, E - 1);
            hp[j] = heads[e]; tp[j] = tails[e]; rp[j] = etype[e];
        }
    }
    const int* hp = (const int*)&hh;
    const int* tp = (const int*)&tt;
    const int* rp = (const int*)&rr;

    const uint32_t c8 = (uint32_t)(l2 * 4);

    // issue all gathers first (8 independent loads in flight)
    uint2 yv[4], tv[4];
    #pragma unroll
    for (int j = 0; j < 4; j++) {
        yv[j] = *(const uint2*)(g_Yh + ((uint32_t)rp[j] * (uint32_t)N + (uint32_t)hp[j]) * 64u + c8);
        tv[j] = *(const uint2*)(g_egoh + (uint32_t)tp[j] * 64u + c8);
    }

    float p[4];
    float tf[4][4];
    #pragma unroll
    for (int j = 0; j < 4; j++) {
        float2 ya = __half22float2(*(__half2*)&yv[j].x);
        float2 yb = __half22float2(*(__half2*)&yv[j].y);
        float2 ta = __half22float2(*(__half2*)&tv[j].x);
        float2 tb = __half22float2(*(__half2*)&tv[j].y);
        tf[j][0] = ta.x; tf[j][1] = ta.y; tf[j][2] = tb.x; tf[j][3] = tb.y;
        p[j] = ya.x * ta.x + ya.y * ta.y + yb.x * tb.x + yb.y * tb.y;
    }
    #pragma unroll
    for (int o = 1; o < 16; o <<= 1) {
        #pragma unroll
        for (int j = 0; j < 4; j++)
            p[j] += __shfl_xor_sync(hmask, p[j], o);
    }

    float ex[4];
    #pragma unroll
    for (int j = 0; j < 4; j++) {
        float s = p[j] > 0.f ? p[j] : 0.01f * p[j];
        ex[j] = __expf(s);
    }

    #pragma unroll
    for (int j = 0; j < 4; j++) {
        if (ebase + j >= E) break;
        if (l2 == 0)
            asm volatile("red.global.add.v2.f32 [%0], {%1, %2};"
                         :: "l"(&g_dencnt[hp[j]]), "f"(ex[j]), "f"(1.0f) : "memory");
        float* op = out + (uint32_t)hp[j] * 64u + c8;
        asm volatile("red.global.add.v4.f32 [%0], {%1, %2, %3, %4};"
                     :: "l"(op), "f"(ex[j] * tf[j][0]), "f"(ex[j] * tf[j][1]),
                        "f"(ex[j] * tf[j][2]), "f"(ex[j] * tf[j][3]) : "memory");
    }
}

// ---- epilogue: divide by den * max(cnt,1), float4 per thread --------------
__global__ void pass3_mean(float4* __restrict__ out4, int N)
{
    int i = blockIdx.x * blockDim.x + threadIdx.x;    // one float4 (4 elems)
    if (i < N * 16) {
        float2 dc = g_dencnt[i >> 4];
        float s = (dc.y > 0.0f) ? __frcp_rn(dc.x * dc.y) : 0.0f;
        float4 v = out4[i];
        v.x *= s; v.y *= s; v.z *= s; v.w *= s;
        out4[i] = v;
    }
}

// ---------------------------------------------------------------------------
extern "C" void kernel_launch(void* const* d_in, const int* in_sizes, int n_in,
                              void* d_out, int out_size)
{
    const float* ego = (const float*)d_in[0];   // [N,64] f32
    const float* Wg  = (const float*)d_in[1];   // [16,64,64] f32
    const int*   ei  = (const int*)d_in[2];     // [2,E] i32
    const int*   et  = (const int*)d_in[3];     // [E] i32
    float* out = (float*)d_out;

    const int N = in_sizes[0] / 64;
    const int E = in_sizes[3];
    const int* heads = ei;
    const int* tails = ei + E;

    cudaFuncSetAttribute(gemm_transform,
                         cudaFuncAttributeMaxDynamicSharedMemorySize, SMEM_SZ);

    const int n_out4 = N * 16;                  // out as float4
    const int n_dc4  = (N * 2 + 3) / 4;         // dencnt as float4
    zero_kernel<<<(n_out4 + 255) / 256, 256>>>((float4*)out, (const float4*)ego,
                                               Wg, n_out4, n_dc4);

    const int tiles = (N + 127) / 128;
    gemm_transform<<<tiles * 4, 256, SMEM_SZ>>>(ego, N);

    // 8 edges per warp, 64 per CTA
    edge_pass<<<(E + 63) / 64, 256>>>(heads, tails, et, out, N, E);

    pass3_mean<<<(n_out4 + 255) / 256, 256>>>((float4*)out, N);
}

// round 17
// speedup vs baseline: 1.4041x; 1.4041x over previous
#include <cuda_runtime.h>
#include <cuda_bf16.h>
#include <cuda_fp16.h>
#include <math.h>
#include <stdint.h>

// ---------------------------------------------------------------------------
// Aggregator: relational graph attention, tensor-core (warp mma.sync) version.
//   Y[r]     = ego @ W[r]            (bf16 HMMA, fp32 accumulate, fp16 store)
//   s_e      = leaky_relu( Y[et_e, h_e] . ego[t_e] )
//   out[n]   = sum_e exp(s_e) * ego[t_e]  /  ( den[n] * max(cnt[n],1) )
// GEMM: serial 16-relation loop per 128-row tile (R11 structure), with the
// per-relation B stage converted to cp.async double-buffering. R16's bug was
// a missing smem base on the in-loop cp.async destination; fixed here.
// ---------------------------------------------------------------------------

#define N_CAP   131072
#define YROWS   102400               // >= N, multiple of 128
__device__ __half g_Yh[16u * YROWS * 64u];     // [R, N, 64] fp16
__device__ __half g_egoh[(size_t)N_CAP * 64];  // [N, 64] fp16 mirror of ego
__device__ float2 g_dencnt[N_CAP];             // (den, cnt) per head node

// pre-transposed W (row n, col k), padded row stride AS, bf16
#define AS 72
__device__ __nv_bfloat16 g_Wt[16 * 64 * AS];

__device__ __forceinline__ uint32_t smem_u32(const void* p) {
    uint32_t a;
    asm("{ .reg .u64 t; cvta.to.shared.u64 t, %1; cvt.u32.u64 %0, t; }"
        : "=r"(a) : "l"(p));
    return a;
}
__device__ __forceinline__ void ldm_x4(uint32_t* r, uint32_t addr) {
    asm volatile("ldmatrix.sync.aligned.m8n8.x4.shared.b16 {%0,%1,%2,%3}, [%4];"
                 : "=r"(r[0]), "=r"(r[1]), "=r"(r[2]), "=r"(r[3]) : "r"(addr));
}
__device__ __forceinline__ void mma_bf16(float* c, const uint32_t* a,
                                         uint32_t b0, uint32_t b1) {
    asm volatile(
        "mma.sync.aligned.m16n8k16.row.col.f32.bf16.bf16.f32 "
        "{%0,%1,%2,%3}, {%4,%5,%6,%7}, {%8,%9}, {%0,%1,%2,%3};"
        : "+f"(c[0]), "+f"(c[1]), "+f"(c[2]), "+f"(c[3])
        : "r"(a[0]), "r"(a[1]), "r"(a[2]), "r"(a[3]), "r"(b0), "r"(b1));
}
__device__ __forceinline__ uint32_t pack2(float x0, float x1) {
    return ((uint32_t)__bfloat16_as_ushort(__float2bfloat16(x1)) << 16)
         | (uint32_t)__bfloat16_as_ushort(__float2bfloat16(x0));
}
__device__ __forceinline__ void cp_async16(uint32_t dst, const void* src) {
    asm volatile("cp.async.cg.shared.global [%0], [%1], 16;"
                 :: "r"(dst), "l"(src) : "memory");
}
#define CP_COMMIT() asm volatile("cp.async.commit_group;" ::: "memory")
#define CP_WAIT(n)  asm volatile("cp.async.wait_group %0;" :: "n"(n) : "memory")

// smem layout (bytes): region0 = A tile, later reused as Y staging
//   (128 rows x AS halves = 18432B); region1 = B double buffer (2 x 9216B)
#define A_OFF   0
#define B_OFF   18432
#define B_BYTES 9216
#define SMEM_SZ (18432 + 2 * B_BYTES + 128)

// ============================ kernels ======================================

// ---- zero out + dencnt + fp16 ego mirror; blocks 0..15 also prep W --------
__global__ void zero_kernel(float4* __restrict__ out4,
                            const float4* __restrict__ ego4,
                            const float* __restrict__ Wg,
                            int n_out4, int n_dc4)
{
    int i = blockIdx.x * blockDim.x + threadIdx.x;
    if (i < n_out4) {
        out4[i] = make_float4(0.f, 0.f, 0.f, 0.f);
        float4 v = ego4[i];
        __half2 h0 = __floats2half2_rn(v.x, v.y);
        __half2 h1 = __floats2half2_rn(v.z, v.w);
        *(uint2*)(g_egoh + (size_t)i * 4) =
            make_uint2(*(uint32_t*)&h0, *(uint32_t*)&h1);
    }
    if (i < n_dc4) ((float4*)g_dencnt)[i] = make_float4(0.f, 0.f, 0.f, 0.f);

    if (blockIdx.x < 16) {           // W transpose to bf16, padded stride
        const int r = blockIdx.x;
        for (int idx = threadIdx.x; idx < 4096; idx += 256) {
            int k = idx >> 6, n = idx & 63;          // W[k][n], coalesced read
            float v = Wg[(size_t)r * 4096 + idx];
            g_Wt[r * 64 * AS + n * AS + k] = __float2bfloat16(v);
        }
    }
}

// ---- GEMM: Y[r] = X @ W[r]; 128-row tile per CTA, cp.async B dbl-buffer ---
__global__ __launch_bounds__(256) void gemm_transform(
    const float* __restrict__ ego, int N)
{
    extern __shared__ __align__(16) char sm[];
    __nv_bfloat16* sh = (__nv_bfloat16*)sm;
    __half* stag = (__half*)sm;                  // staging aliases A region
    const uint32_t smb = smem_u32(sm);

    const int tid  = threadIdx.x;
    const int wid  = tid >> 5;
    const int lane = tid & 31;
    const int tile = blockIdx.x;
    const int rows = min(128, N - tile * 128);

    // --- kick off async B(0) stage ------------------------------------------
    {
        #pragma unroll
        for (int k = 0; k < 3; k++) {
            int i = tid + k * 256;
            if (i < 576)
                cp_async16(smb + B_OFF + (uint32_t)i * 16u,
                           (const char*)g_Wt + i * 16);
        }
        CP_COMMIT();
    }

    // --- stage A tile (ego rows) as bf16, zero-padded ----------------------
    for (int i = tid * 2; i < 128 * 64; i += 512) {
        int row = i >> 6, col = i & 63;
        float v0 = 0.f, v1 = 0.f;
        if (row < rows) {
            const float2 v = *(const float2*)(ego + ((size_t)(tile * 128 + row)) * 64 + col);
            v0 = v.x; v1 = v.y;
        }
        *(uint32_t*)(sh + row * AS + col) = pack2(v0, v1);
    }
    __syncthreads();

    // --- per-warp A fragment: 16 rows x K=64, held in registers ------------
    const int m0   = wid * 16;
    const int frow = (lane & 7) + ((lane >> 3) & 1) * 8;
    const int fcol = (lane >> 4) * 8;
    uint32_t Af[4][4];
    #pragma unroll
    for (int kt = 0; kt < 4; kt++) {
        uint32_t off = (uint32_t)((m0 + frow) * AS + kt * 16 + fcol) * 2;
        ldm_x4(Af[kt], smb + A_OFF + off);
    }

    const int g  = lane >> 2;         // output row within 8-group
    const int tq = lane & 3;          // output col pair

    for (int r = 0; r < 16; r++) {
        const uint32_t bcur = smb + B_OFF + (uint32_t)(r & 1) * B_BYTES;

        // issue async stage of B(r+1) into the alternate buffer
        if (r < 15) {
            const uint32_t bnxt = smb + B_OFF + (uint32_t)((r + 1) & 1) * B_BYTES;
            const char* src = (const char*)(g_Wt + (r + 1) * 64 * AS);
            #pragma unroll
            for (int k = 0; k < 3; k++) {
                int i = tid + k * 256;
                if (i < 576)
                    cp_async16(bnxt + (uint32_t)i * 16u, src + i * 16);
            }
            CP_COMMIT();
            CP_WAIT(1);               // B(r) complete; B(r+1) may be in flight
        } else {
            CP_WAIT(0);
        }
        __syncthreads();   // B(r) visible to all; staging free (prev STG done)

        float acc[8][4];
        #pragma unroll
        for (int i = 0; i < 8; i++)
            #pragma unroll
            for (int j = 0; j < 4; j++) acc[i][j] = 0.f;

        #pragma unroll
        for (int nt = 0; nt < 4; nt++) {
            #pragma unroll
            for (int kt = 0; kt < 4; kt++) {
                uint32_t boff = (uint32_t)((nt * 16 + frow) * AS + kt * 16 + fcol) * 2;
                uint32_t Bf[4];
                ldm_x4(Bf, bcur + boff);
                mma_bf16(acc[2 * nt],     Af[kt], Bf[0], Bf[2]);
                mma_bf16(acc[2 * nt + 1], Af[kt], Bf[1], Bf[3]);
            }
        }

        // --- STS fragments to staging (padded stride AS -> no row aliasing)
        {
            int row0 = m0 + g;
            #pragma unroll
            for (int nt8 = 0; nt8 < 8; nt8++) {
                int col = nt8 * 8 + tq * 2;
                __half2 ha = __floats2half2_rn(acc[nt8][0], acc[nt8][1]);
                __half2 hb = __floats2half2_rn(acc[nt8][2], acc[nt8][3]);
                *(__half2*)(stag + row0 * AS + col)       = ha;
                *(__half2*)(stag + (row0 + 8) * AS + col) = hb;
            }
        }
        __syncthreads();

        // --- coalesced Y writeback: full 128B lines ------------------------
        {
            uint32_t ybase = ((uint32_t)r * (uint32_t)N + (uint32_t)(tile * 128)) * 64u;
            #pragma unroll
            for (int q = 0; q < 4; q++) {
                int i = tid + q * 256;            // 1024 uint4 total
                int row = i >> 3, seg = i & 7;
                if (row < rows) {
                    uint4 v = *(const uint4*)(stag + row * AS + seg * 8);
                    *(uint4*)(g_Yh + ybase + (uint32_t)row * 64u + seg * 8) = v;
                }
            }
        }
        // next iteration's post-wait barrier orders staging reuse
    }
}

// ---- fused edge pass: 8 edges/warp (4 per half), fp16 gathers -------------
__global__ __launch_bounds__(256) void edge_pass(
    const int*   __restrict__ heads,
    const int*   __restrict__ tails,
    const int*   __restrict__ etype,
    float*       __restrict__ out,
    int N, int E)
{
    const int warp = (blockIdx.x * 256 + threadIdx.x) >> 5;
    const int lane = threadIdx.x & 31;
    const int half = lane >> 4;
    const int l2   = lane & 15;
    const unsigned hmask = 0xFFFFu << (half * 16);

    const int ebase = warp * 8 + half * 4;     // this half-warp: 4 edges
    if (ebase >= E) return;

    int4 hh, tt, rr;
    if (ebase + 3 < E) {
        hh = *(const int4*)(heads + ebase);
        tt = *(const int4*)(tails + ebase);
        rr = *(const int4*)(etype + ebase);
    } else {
        int* hp = (int*)&hh; int* tp = (int*)&tt; int* rp = (int*)&rr;
        #pragma unroll
        for (int j = 0; j < 4; j++) {
            int e = min(ebase + j, E - 1);
            hp[j] = heads[e]; tp[j] = tails[e]; rp[j] = etype[e];
        }
    }
    const int* hp = (const int*)&hh;
    const int* tp = (const int*)&tt;
    const int* rp = (const int*)&rr;

    const uint32_t c8 = (uint32_t)(l2 * 4);

    // issue all gathers first (8 independent loads in flight)
    uint2 yv[4], tv[4];
    #pragma unroll
    for (int j = 0; j < 4; j++) {
        yv[j] = *(const uint2*)(g_Yh + ((uint32_t)rp[j] * (uint32_t)N + (uint32_t)hp[j]) * 64u + c8);
        tv[j] = *(const uint2*)(g_egoh + (uint32_t)tp[j] * 64u + c8);
    }

    float p[4];
    float tf[4][4];
    #pragma unroll
    for (int j = 0; j < 4; j++) {
        float2 ya = __half22float2(*(__half2*)&yv[j].x);
        float2 yb = __half22float2(*(__half2*)&yv[j].y);
        float2 ta = __half22float2(*(__half2*)&tv[j].x);
        float2 tb = __half22float2(*(__half2*)&tv[j].y);
        tf[j][0] = ta.x; tf[j][1] = ta.y; tf[j][2] = tb.x; tf[j][3] = tb.y;
        p[j] = ya.x * ta.x + ya.y * ta.y + yb.x * tb.x + yb.y * tb.y;
    }
    #pragma unroll
    for (int o = 1; o < 16; o <<= 1) {
        #pragma unroll
        for (int j = 0; j < 4; j++)
            p[j] += __shfl_xor_sync(hmask, p[j], o);
    }

    float ex[4];
    #pragma unroll
    for (int j = 0; j < 4; j++) {
        float s = p[j] > 0.f ? p[j] : 0.01f * p[j];
        ex[j] = __expf(s);
    }

    #pragma unroll
    for (int j = 0; j < 4; j++) {
        if (ebase + j >= E) break;
        if (l2 == 0)
            asm volatile("red.global.add.v2.f32 [%0], {%1, %2};"
                         :: "l"(&g_dencnt[hp[j]]), "f"(ex[j]), "f"(1.0f) : "memory");
        float* op = out + (uint32_t)hp[j] * 64u + c8;
        asm volatile("red.global.add.v4.f32 [%0], {%1, %2, %3, %4};"
                     :: "l"(op), "f"(ex[j] * tf[j][0]), "f"(ex[j] * tf[j][1]),
                        "f"(ex[j] * tf[j][2]), "f"(ex[j] * tf[j][3]) : "memory");
    }
}

// ---- epilogue: divide by den * max(cnt,1), float4 per thread --------------
__global__ void pass3_mean(float4* __restrict__ out4, int N)
{
    int i = blockIdx.x * blockDim.x + threadIdx.x;    // one float4 (4 elems)
    if (i < N * 16) {
        float2 dc = g_dencnt[i >> 4];
        float s = (dc.y > 0.0f) ? __frcp_rn(dc.x * dc.y) : 0.0f;
        float4 v = out4[i];
        v.x *= s; v.y *= s; v.z *= s; v.w *= s;
        out4[i] = v;
    }
}

// ---------------------------------------------------------------------------
extern "C" void kernel_launch(void* const* d_in, const int* in_sizes, int n_in,
                              void* d_out, int out_size)
{
    const float* ego = (const float*)d_in[0];   // [N,64] f32
    const float* Wg  = (const float*)d_in[1];   // [16,64,64] f32
    const int*   ei  = (const int*)d_in[2];     // [2,E] i32
    const int*   et  = (const int*)d_in[3];     // [E] i32
    float* out = (float*)d_out;

    const int N = in_sizes[0] / 64;
    const int E = in_sizes[3];
    const int* heads = ei;
    const int* tails = ei + E;

    cudaFuncSetAttribute(gemm_transform,
                         cudaFuncAttributeMaxDynamicSharedMemorySize, SMEM_SZ);

    const int n_out4 = N * 16;                  // out as float4
    const int n_dc4  = (N * 2 + 3) / 4;         // dencnt as float4
    zero_kernel<<<(n_out4 + 255) / 256, 256>>>((float4*)out, (const float4*)ego,
                                               Wg, n_out4, n_dc4);

    const int tiles = (N + 127) / 128;
    gemm_transform<<<tiles, 256, SMEM_SZ>>>(ego, N);

    // 8 edges per warp, 64 per CTA
    edge_pass<<<(E + 63) / 64, 256>>>(heads, tails, et, out, N, E);

    pass3_mean<<<(n_out4 + 255) / 256, 256>>>((float4*)out, N);
}